// round 14
// baseline (speedup 1.0000x reference)
#include <cuda_runtime.h>
#include <cuda_fp16.h>
#include <stdint.h>

#define C_DIM   256
#define NGROUP  32
#define CPG     8
#define NET     7
#define NBATCH  8
#define GN_EPS  1e-5f
#define MAXN    100000
#define MAXE    1048576
#define N7MAX   (MAXN * NET)
#define NPB     128
#define SCAN_B  2048

// ---------------- scratch ----------------
__device__ __half  g_h  [(size_t)MAXN * C_DIM];            // fp16 GEMM input
__device__ __half  g_acch[(size_t)MAXN * C_DIM];           // conv1 output (fp16)
__device__ __half  g_Y  [(size_t)(N7MAX + 1024) * C_DIM];  // compacted fp16 intermediate
__device__ __half  g_Wb1[NET * C_DIM * C_DIM];             // packed W1: [t][n][k] fp16
__device__ __half  g_Wb2[NET * C_DIM * C_DIM];
__device__ int     g_cnt[MAXN * NET];      // per (row, type) in-degree
__device__ int     g_rowcnt[MAXN];
__device__ int     g_offs[MAXN];
__device__ int     g_cur[MAXN];
__device__ int     g_blksum[64];
__device__ int     g_eperm[MAXE];          // (pos<<3) | type
// --- compaction state ---
__device__ int     g_need[N7MAX];
__device__ int     g_cpos[N7MAX];
__device__ int     g_blksum2[512];
__device__ int     g_pos [N7MAX];
__device__ int     g_clist[N7MAX + 1024];
__device__ int     g_tpadA[8];
__device__ int     g_tstart[8];
__device__ int     g_mtotal;
// --- GN state ---
__device__ float   g_s1 [NBATCH * NGROUP];
__device__ float   g_s2 [NBATCH * NGROUP];
__device__ float   g_mean[NBATCH * NGROUP];
__device__ float   g_istd[NBATCH * NGROUP];
__device__ float   g_bcnt[NBATCH];         // maintained zero-at-entry across launches

// ---------------- init (+ batch count fused) ----------------
__global__ void k_init(const int* __restrict__ bid, int N, int n7) {
    __shared__ int sc[NBATCH];
    if (threadIdx.x < NBATCH) sc[threadIdx.x] = 0;
    __syncthreads();
    int i = blockIdx.x * blockDim.x + threadIdx.x;
    if (i < n7) { g_cnt[i] = 0; g_need[i] = 0; }
    if (i < n7 + 1024) g_clist[i] = -1;
    if (i < N) { g_cur[i] = 0; atomicAdd(&sc[bid[i]], 1); }
    if (i < NBATCH * NGROUP) { g_s1[i] = 0.f; g_s2[i] = 0.f; }
    __syncthreads();
    if (threadIdx.x < NBATCH && sc[threadIdx.x] > 0)
        atomicAdd(&g_bcnt[threadIdx.x], (float)sc[threadIdx.x]);
}

// ---------------- W pack+transpose, both weights in one launch ----------------
__global__ void k_wpackT2(const float* __restrict__ W1, const float* __restrict__ W2,
                          __half* __restrict__ Wb1, __half* __restrict__ Wb2) {
    __shared__ float tile[32][33];
    int z = blockIdx.z;
    const float* W = (z < NET) ? W1 : W2;
    __half* Wb     = (z < NET) ? Wb1 : Wb2;
    int t = (z < NET) ? z : z - NET;
    int k0 = blockIdx.x * 32, n0 = blockIdx.y * 32;
    for (int j = threadIdx.y; j < 32; j += 8)
        tile[j][threadIdx.x] = W[(size_t)(t * 256 + k0 + j) * C_DIM + n0 + threadIdx.x];
    __syncthreads();
    for (int j = threadIdx.y; j < 32; j += 8)
        Wb[((size_t)t * 256 + n0 + j) * C_DIM + k0 + threadIdx.x] =
            __float2half_rn(tile[threadIdx.x][j]);
}

// ---------------- GN ----------------
__global__ void k_gnstats(const float* __restrict__ src, const int* __restrict__ bid, int N) {
    __shared__ int sbid[NPB];
    int n0 = blockIdx.x * NPB;
    int nmax = min(N - n0, NPB);
    for (int i = threadIdx.x; i < nmax; i += blockDim.x) sbid[i] = bid[n0 + i];
    __syncthreads();
    int c = threadIdx.x;
    int g = c >> 3;
    float ls1 = 0.f, ls2 = 0.f;
    int cur = sbid[0];
    for (int i = 0; i < nmax; ++i) {
        int b = sbid[i];
        if (b != cur) {
            atomicAdd(&g_s1[cur * NGROUP + g], ls1);
            atomicAdd(&g_s2[cur * NGROUP + g], ls2);
            ls1 = 0.f; ls2 = 0.f; cur = b;
        }
        float v = src[(size_t)(n0 + i) * C_DIM + c];
        ls1 += v; ls2 += v * v;
    }
    atomicAdd(&g_s1[cur * NGROUP + g], ls1);
    atomicAdd(&g_s2[cur * NGROUP + g], ls2);
}
__global__ void k_gnfinal(int zero_bcnt) {
    int i = threadIdx.x;
    int b = i >> 5;
    float n  = g_bcnt[b] * (float)CPG;
    float ic = 1.0f / (n + GN_EPS);
    float s1 = g_s1[i], s2 = g_s2[i];
    float m  = s1 * ic;
    float var = ic * (s2 - 2.f * m * s1 + m * m * n);
    g_mean[i] = m;
    g_istd[i] = rsqrtf(var + GN_EPS);
    __syncthreads();
    g_s1[i] = 0.f; g_s2[i] = 0.f;
    if (zero_bcnt && i < NBATCH) g_bcnt[i] = 0.f;
}
__global__ void k_gn_silu_h(const float* __restrict__ src, __half* __restrict__ dst,
                            const float* __restrict__ w, const float* __restrict__ bb,
                            const int* __restrict__ bid, int N) {
    int i = blockIdx.x * blockDim.x + threadIdx.x;
    int total = N * (C_DIM / 4);
    if (i >= total) return;
    int n  = i >> 6;
    int c4 = (i & 63) << 2;
    int b  = bid[n];
    int s  = b * NGROUP + (c4 >> 3);
    float m  = g_mean[s], is = g_istd[s];
    float4 xv = ((const float4*)src)[i];
    float4 wv = ((const float4*)w)[c4 >> 2];
    float4 bv = ((const float4*)bb)[c4 >> 2];
    float v0 = (xv.x - m) * is * wv.x + bv.x; v0 = v0 / (1.f + expf(-v0));
    float v1 = (xv.y - m) * is * wv.y + bv.y; v1 = v1 / (1.f + expf(-v1));
    float v2 = (xv.z - m) * is * wv.z + bv.z; v2 = v2 / (1.f + expf(-v2));
    float v3 = (xv.w - m) * is * wv.w + bv.w; v3 = v3 / (1.f + expf(-v3));
    __half2 h[2];
    h[0] = __floats2half2_rn(v0, v1);
    h[1] = __floats2half2_rn(v2, v3);
    *(uint2*)(dst + (size_t)n * C_DIM + c4) = *(uint2*)h;
}
__global__ void k_gn_silu_hh(const __half* __restrict__ src, __half* __restrict__ dst,
                             const float* __restrict__ w, const float* __restrict__ bb,
                             const int* __restrict__ bid, int N) {
    int i = blockIdx.x * blockDim.x + threadIdx.x;
    int total = N * (C_DIM / 4);
    if (i >= total) return;
    int n  = i >> 6;
    int c4 = (i & 63) << 2;
    int b  = bid[n];
    int s  = b * NGROUP + (c4 >> 3);
    float m  = g_mean[s], is = g_istd[s];
    uint2 raw = *(const uint2*)(src + (size_t)n * C_DIM + c4);
    const __half2* hp = (const __half2*)&raw;
    float2 f0 = __half22float2(hp[0]);
    float2 f1 = __half22float2(hp[1]);
    float4 wv = ((const float4*)w)[c4 >> 2];
    float4 bv = ((const float4*)bb)[c4 >> 2];
    float v0 = (f0.x - m) * is * wv.x + bv.x; v0 = v0 / (1.f + expf(-v0));
    float v1 = (f0.y - m) * is * wv.y + bv.y; v1 = v1 / (1.f + expf(-v1));
    float v2 = (f1.x - m) * is * wv.z + bv.z; v2 = v2 / (1.f + expf(-v2));
    float v3 = (f1.y - m) * is * wv.w + bv.w; v3 = v3 / (1.f + expf(-v3));
    __half2 h[2];
    h[0] = __floats2half2_rn(v0, v1);
    h[1] = __floats2half2_rn(v2, v3);
    *(uint2*)(dst + (size_t)n * C_DIM + c4) = *(uint2*)h;
}

// ---------------- edge count + needed-bitmap ----------------
__global__ void k_ecount2(const int* __restrict__ erow, const int* __restrict__ ecol,
                          const int* __restrict__ et, int E, int N) {
    int e = blockIdx.x * blockDim.x + threadIdx.x;
    if (e < E) {
        int r = erow[e], t = et[e];
        atomicAdd(&g_cnt[r * NET + t], 1);
        g_need[t * N + ecol[e]] = 1;
    }
}
__global__ void k_scan1(int N) {
    __shared__ int sh[256];
    int base = blockIdx.x * SCAN_B;
    int tid = threadIdx.x;
    int vals[8];
    int s = 0;
    #pragma unroll
    for (int j = 0; j < 8; ++j) {
        int idx = base + tid * 8 + j;
        int v = 0;
        if (idx < N) {
            const int* cp = &g_cnt[idx * NET];
            #pragma unroll
            for (int q = 0; q < NET; ++q) v += cp[q];
            g_rowcnt[idx] = v;
        }
        vals[j] = s;
        s += v;
    }
    sh[tid] = s;
    __syncthreads();
    for (int off = 1; off < 256; off <<= 1) {
        int t = (tid >= off) ? sh[tid - off] : 0;
        __syncthreads();
        sh[tid] += t;
        __syncthreads();
    }
    int tb = tid ? sh[tid - 1] : 0;
    #pragma unroll
    for (int j = 0; j < 8; ++j) {
        int idx = base + tid * 8 + j;
        if (idx < N) g_offs[idx] = tb + vals[j];
    }
    if (tid == 255) g_blksum[blockIdx.x] = sh[255];
}
__global__ void k_scan2(int nb) {
    __shared__ int sh[64];
    int t = threadIdx.x;
    sh[t] = (t < nb) ? g_blksum[t] : 0;
    __syncthreads();
    for (int off = 1; off < 64; off <<= 1) {
        int v = (t >= off) ? sh[t - off] : 0;
        __syncthreads();
        sh[t] += v;
        __syncthreads();
    }
    if (t < nb) g_blksum[t] = t ? sh[t - 1] : 0;
}
__global__ void k_scan1b(int M) {
    __shared__ int sh[256];
    int base = blockIdx.x * SCAN_B;
    int tid = threadIdx.x;
    int vals[8];
    int s = 0;
    #pragma unroll
    for (int j = 0; j < 8; ++j) {
        int idx = base + tid * 8 + j;
        int v = (idx < M && g_need[idx]) ? 1 : 0;
        vals[j] = s;
        s += v;
    }
    sh[tid] = s;
    __syncthreads();
    for (int off = 1; off < 256; off <<= 1) {
        int t = (tid >= off) ? sh[tid - off] : 0;
        __syncthreads();
        sh[tid] += t;
        __syncthreads();
    }
    int tb = tid ? sh[tid - 1] : 0;
    #pragma unroll
    for (int j = 0; j < 8; ++j) {
        int idx = base + tid * 8 + j;
        if (idx < M) g_cpos[idx] = tb + vals[j];
    }
    if (tid == 255) g_blksum2[blockIdx.x] = sh[255];
}
__global__ void k_scan2b(int nb, int N, int n7) {
    __shared__ int sh[512];
    int t = threadIdx.x;
    sh[t] = (t < nb) ? g_blksum2[t] : 0;
    __syncthreads();
    for (int off = 1; off < 512; off <<= 1) {
        int v = (t >= off) ? sh[t - off] : 0;
        __syncthreads();
        sh[t] += v;
        __syncthreads();
    }
    if (t < nb) g_blksum2[t] = t ? sh[t - 1] : 0;
    __syncthreads();
    if (t == 0) {
        int tstart[8];
        for (int q = 0; q < NET; ++q) {
            int idx = q * N;
            tstart[q] = g_cpos[idx] + g_blksum2[idx / SCAN_B];
        }
        int last = n7 - 1;
        tstart[7] = g_cpos[last] + g_blksum2[last / SCAN_B] + (g_need[last] ? 1 : 0);
        int tp = 0;
        for (int q = 0; q < NET; ++q) {
            g_tstart[q] = tstart[q];
            g_tpadA[q] = tp;
            tp += (tstart[q + 1] - tstart[q] + 127) & ~127;
        }
        g_tstart[7] = tstart[7];
        g_tpadA[7] = tp;
        g_mtotal = tp;
    }
}
__global__ void k_fillpos(int N, int n7) {
    int i = blockIdx.x * blockDim.x + threadIdx.x;
    if (i >= n7 || !g_need[i]) return;
    int t = i / N, c = i - t * N;
    int pos = g_tpadA[t] + g_cpos[i] + g_blksum2[i / SCAN_B] - g_tstart[t];
    g_pos[i] = pos;
    g_clist[pos] = c;
}
__global__ void k_escatter(const int* __restrict__ erow, const int* __restrict__ ecol,
                           const int* __restrict__ et, int E, int N) {
    int e = blockIdx.x * blockDim.x + threadIdx.x;
    if (e >= E) return;
    int r = erow[e], t = et[e];
    int posIdx = g_offs[r] + g_blksum[r >> 11] + atomicAdd(&g_cur[r], 1);
    int pos = g_pos[t * N + ecol[e]];
    g_eperm[posIdx] = (pos << 3) | t;
}

// ---------------- fp16 GEMM: 128 thr / 4 warps, warp tile 64x64, 3-stage cp.async ----------------
#define BM 128
#define BN 128
#define BK 32
#define KSTR 40
#define TILE_B (128 * KSTR * 2)
#define STAGE_B (2 * TILE_B)
#define NSTAGE 3
#define EPS_LD 136

__device__ __forceinline__ void mma_f16(float* d, const uint32_t* a, uint32_t b0, uint32_t b1) {
    asm volatile("mma.sync.aligned.m16n8k16.row.col.f32.f16.f16.f32 "
        "{%0,%1,%2,%3}, {%4,%5,%6,%7}, {%8,%9}, {%0,%1,%2,%3};\n"
        : "+f"(d[0]), "+f"(d[1]), "+f"(d[2]), "+f"(d[3])
        : "r"(a[0]), "r"(a[1]), "r"(a[2]), "r"(a[3]), "r"(b0), "r"(b1));
}
__device__ __forceinline__ void ldsm_x4(uint32_t* r, uint32_t addr) {
    asm volatile("ldmatrix.sync.aligned.m8n8.x4.shared.b16 {%0,%1,%2,%3}, [%4];\n"
        : "=r"(r[0]), "=r"(r[1]), "=r"(r[2]), "=r"(r[3]) : "r"(addr));
}

__global__ __launch_bounds__(128, 2)
void k_gemm_h(const __half* __restrict__ A, const __half* __restrict__ Wb,
              __half* __restrict__ Y) {
    int m0 = blockIdx.y * BM;
    if (m0 >= g_mtotal) return;

    __shared__ __align__(16) char sm[NSTAGE * STAGE_B];   // 61440 B

    int tid  = threadIdx.x;
    int warp = tid >> 5, lane = tid & 31;
    int n0 = blockIdx.x * BN;

    int t = 0;
    #pragma unroll
    for (int q = 1; q < NET; ++q) t += (m0 >= g_tpadA[q]) ? 1 : 0;
    const __half* gB = Wb + ((size_t)t * 256 + n0) * C_DIM;

    int wm = warp >> 1, wn = warp & 1;      // 2x2 warps, warp tile 64m x 64n
    int mBase = wm * 64, nBase = wn * 64;
    int grp = lane >> 2, tig = lane & 3;
    int mi = lane >> 3, lr = lane & 7;

    uint32_t sbase = (uint32_t)__cvta_generic_to_shared(sm);

    float acc[4][8][4];
    #pragma unroll
    for (int i = 0; i < 4; ++i)
        #pragma unroll
        for (int j = 0; j < 8; ++j)
            #pragma unroll
            for (int q = 0; q < 4; ++q) acc[i][j][q] = 0.f;

    int colA = g_clist[m0 + tid];           // one A row per thread

    auto issue = [&](int st, int kb) {
        uint32_t sa = sbase + st * STAGE_B;
        uint32_t sb = sa + TILE_B;
        int zA = (colA >= 0) ? 16 : 0;
        const __half* srcA = (colA >= 0) ? (A + (size_t)colA * C_DIM + kb) : A;
        const __half* srcB = gB + (size_t)tid * C_DIM + kb;
        #pragma unroll
        for (int cQ = 0; cQ < 4; ++cQ) {
            uint32_t dA = sa + tid * (KSTR * 2) + cQ * 16;
            asm volatile("cp.async.cg.shared.global [%0], [%1], 16, %2;\n"
                :: "r"(dA), "l"(srcA + cQ * 8), "r"(zA) : "memory");
            uint32_t dB = sb + tid * (KSTR * 2) + cQ * 16;
            asm volatile("cp.async.cg.shared.global [%0], [%1], 16, 16;\n"
                :: "r"(dB), "l"(srcB + cQ * 8) : "memory");
        }
        asm volatile("cp.async.commit_group;\n" ::: "memory");
    };

    auto compute = [&](int st) {
        uint32_t sa = sbase + st * STAGE_B;
        uint32_t sb = sa + TILE_B;
        #pragma unroll
        for (int ks = 0; ks < 2; ++ks) {
            int k0 = ks * 16;
            uint32_t a[4][4];
            #pragma unroll
            for (int im = 0; im < 4; ++im) {
                int row = mBase + im * 16 + ((mi & 1) << 3) + lr;
                int col = k0 + ((mi >> 1) << 3);
                ldsm_x4(a[im], sa + (uint32_t)(row * KSTR + col) * 2);
            }
            #pragma unroll
            for (int nb = 0; nb < 4; ++nb) {
                uint32_t b[4];
                int row = nBase + nb * 16 + ((mi >> 1) << 3) + lr;
                int col = k0 + ((mi & 1) << 3);
                ldsm_x4(b, sb + (uint32_t)(row * KSTR + col) * 2);
                #pragma unroll
                for (int im = 0; im < 4; ++im) {
                    mma_f16(acc[im][nb * 2],     a[im], b[0], b[1]);
                    mma_f16(acc[im][nb * 2 + 1], a[im], b[2], b[3]);
                }
            }
        }
    };

    issue(0, 0);
    issue(1, BK);
    #pragma unroll
    for (int it = 0; it < 8; ++it) {
        if (it + 2 < 8) {
            asm volatile("cp.async.wait_group 1;\n" ::: "memory");
        } else {
            asm volatile("cp.async.wait_group 0;\n" ::: "memory");
        }
        __syncthreads();
        if (it + 2 < 8) issue((it + 2) % 3, (it + 2) * BK);
        compute(it % 3);
    }

    // ---- epilogue: stage via smem, coalesced uint4 stores ----
    __syncthreads();
    __half* ep = (__half*)sm;
    #pragma unroll
    for (int im = 0; im < 4; ++im) {
        int r = mBase + im * 16 + grp;
        #pragma unroll
        for (int in = 0; in < 8; ++in) {
            int cc = nBase + in * 8 + tig * 2;
            *(__half2*)(ep + r * EPS_LD + cc) =
                __floats2half2_rn(acc[im][in][0], acc[im][in][1]);
            *(__half2*)(ep + (r + 8) * EPS_LD + cc) =
                __floats2half2_rn(acc[im][in][2], acc[im][in][3]);
        }
    }
    __syncthreads();
    #pragma unroll
    for (int j = 0; j < 16; ++j) {
        int idx = tid + j * 128;          // 0..2047
        int row = idx >> 4, u = idx & 15;
        *(uint4*)(Y + (size_t)(m0 + row) * C_DIM + n0 + u * 8) =
            *(const uint4*)(ep + row * EPS_LD + u * 8);
    }
}

// ---------------- conv1 gather: fp16 out + fused GN2 stats (lane == group) ----------------
__global__ void k_gather_gn(const __half* __restrict__ Y, __half* __restrict__ outh,
                            const int* __restrict__ bid, int N) {
    __shared__ float sh1[NBATCH * NGROUP], sh2[NBATCH * NGROUP];
    int tid = threadIdx.x;
    sh1[tid] = 0.f; sh2[tid] = 0.f;
    __syncthreads();

    int w = (blockIdx.x * blockDim.x + tid) >> 5;
    int lane = tid & 31;
    if (w < N) {
        int beg = g_offs[w] + g_blksum[w >> 11];
        int deg = g_rowcnt[w];
        const int* cntp = &g_cnt[w * NET];
        float acc[8] = {0.f, 0.f, 0.f, 0.f, 0.f, 0.f, 0.f, 0.f};
        for (int j = 0; j < deg; ++j) {
            int p = g_eperm[beg + j];
            int pos = p >> 3, t = p & 7;
            float inv = 1.f / (float)cntp[t];
            uint4 v = *((const uint4*)(Y + (size_t)pos * C_DIM) + lane);
            const __half2* h = (const __half2*)&v;
            #pragma unroll
            for (int q = 0; q < 4; ++q) {
                float2 f = __half22float2(h[q]);
                acc[q * 2 + 0] += f.x * inv;
                acc[q * 2 + 1] += f.y * inv;
            }
        }
        __half2 ho[4];
        #pragma unroll
        for (int q = 0; q < 4; ++q)
            ho[q] = __floats2half2_rn(acc[q * 2], acc[q * 2 + 1]);
        *(uint4*)(outh + (size_t)w * C_DIM + lane * 8) = *(uint4*)ho;

        float ls1 = 0.f, ls2 = 0.f;
        #pragma unroll
        for (int q = 0; q < 8; ++q) { ls1 += acc[q]; ls2 += acc[q] * acc[q]; }
        int b = bid[w];
        atomicAdd(&sh1[b * NGROUP + lane], ls1);
        atomicAdd(&sh2[b * NGROUP + lane], ls2);
    }
    __syncthreads();
    float v1 = sh1[tid], v2 = sh2[tid];
    if (v1 != 0.f) atomicAdd(&g_s1[tid], v1);
    if (v2 != 0.f) atomicAdd(&g_s2[tid], v2);
}

// ---------------- conv2 gather: fp32 out + residual ----------------
__global__ void k_gather(const __half* __restrict__ Y, const float* __restrict__ resid,
                         float* __restrict__ out, int N) {
    int w = (blockIdx.x * blockDim.x + threadIdx.x) >> 5;
    int lane = threadIdx.x & 31;
    if (w >= N) return;
    int beg = g_offs[w] + g_blksum[w >> 11];
    int deg = g_rowcnt[w];
    const int* cntp = &g_cnt[w * NET];

    float acc[8] = {0.f, 0.f, 0.f, 0.f, 0.f, 0.f, 0.f, 0.f};
    for (int j = 0; j < deg; ++j) {
        int p = g_eperm[beg + j];
        int pos = p >> 3, t = p & 7;
        float inv = 1.f / (float)cntp[t];
        uint4 v = *((const uint4*)(Y + (size_t)pos * C_DIM) + lane);
        const __half2* h = (const __half2*)&v;
        #pragma unroll
        for (int q = 0; q < 4; ++q) {
            float2 f = __half22float2(h[q]);
            acc[q * 2 + 0] += f.x * inv;
            acc[q * 2 + 1] += f.y * inv;
        }
    }
    const float* rp = resid + (size_t)w * C_DIM + lane * 8;
    float4 r0 = *(const float4*)rp, r1 = *(const float4*)(rp + 4);
    acc[0] += r0.x; acc[1] += r0.y; acc[2] += r0.z; acc[3] += r0.w;
    acc[4] += r1.x; acc[5] += r1.y; acc[6] += r1.z; acc[7] += r1.w;
    float* orow = out + (size_t)w * C_DIM + lane * 8;
    *(float4*)orow       = make_float4(acc[0], acc[1], acc[2], acc[3]);
    *(float4*)(orow + 4) = make_float4(acc[4], acc[5], acc[6], acc[7]);
}

// ---------------- launch ----------------
extern "C" void kernel_launch(void* const* d_in, const int* in_sizes, int n_in,
                              void* d_out, int out_size) {
    const float* x    = (const float*)d_in[0];
    const float* gn1w = (const float*)d_in[1];
    const float* gn1b = (const float*)d_in[2];
    const float* w1   = (const float*)d_in[3];
    const float* gn2w = (const float*)d_in[4];
    const float* gn2b = (const float*)d_in[5];
    const float* w2   = (const float*)d_in[6];
    const int*   eidx = (const int*)d_in[7];
    const int*   et   = (const int*)d_in[8];
    const int*   bid  = (const int*)d_in[9];

    int N = in_sizes[0] / C_DIM;
    int E = in_sizes[8];
    const int* erow = eidx;
    const int* ecol = eidx + E;

    __half *p_h, *p_acch, *p_Y, *p_Wb1, *p_Wb2;
    cudaGetSymbolAddress((void**)&p_h,    g_h);
    cudaGetSymbolAddress((void**)&p_acch, g_acch);
    cudaGetSymbolAddress((void**)&p_Y,    g_Y);
    cudaGetSymbolAddress((void**)&p_Wb1,  g_Wb1);
    cudaGetSymbolAddress((void**)&p_Wb2,  g_Wb2);

    int n7 = N * NET;
    int t4 = N * (C_DIM / 4);
    int gnBlocks = (N + NPB - 1) / NPB;
    int nbScan  = (N + SCAN_B - 1) / SCAN_B;
    int nbScanB = (n7 + SCAN_B - 1) / SCAN_B;
    int maxYBlocks = (n7 + NET * 128 + BM - 1) / BM;
    dim3 gemmGrid(2, maxYBlocks);
    int gatherBlocks = (N + 7) / 8;
    dim3 wtGrid(8, 8, 2 * NET), wtBlock(32, 8);

    // forked side stream so the CSR/compaction branch runs concurrently with GN1
    cudaStream_t s2;
    cudaStreamCreateWithFlags(&s2, cudaStreamNonBlocking);
    cudaEvent_t evFork, evA, evB;
    cudaEventCreateWithFlags(&evFork, cudaEventDisableTiming);
    cudaEventCreateWithFlags(&evA, cudaEventDisableTiming);
    cudaEventCreateWithFlags(&evB, cudaEventDisableTiming);

    // --- common init ---
    k_init<<<(n7 + 1024 + 255) / 256, 256>>>(bid, N, n7);
    cudaEventRecord(evFork, 0);
    cudaStreamWaitEvent(s2, evFork, 0);

    // --- branch A (s2): CSR + compaction ---
    k_ecount2<<<(E + 255) / 256, 256, 0, s2>>>(erow, ecol, et, E, N);
    k_scan1<<<nbScan, 256, 0, s2>>>(N);
    k_scan2<<<1, 64, 0, s2>>>(nbScan);
    k_scan1b<<<nbScanB, 256, 0, s2>>>(n7);
    k_scan2b<<<1, 512, 0, s2>>>(nbScanB, N, n7);
    k_fillpos<<<(n7 + 255) / 256, 256, 0, s2>>>(N, n7);
    cudaEventRecord(evA, s2);              // GEMM needs tpadA/mtotal/clist
    k_escatter<<<(E + 255) / 256, 256, 0, s2>>>(erow, ecol, et, E, N);
    cudaEventRecord(evB, s2);              // gathers need eperm

    // --- branch B (main): W pack + GN1 + silu ---
    k_wpackT2<<<wtGrid, wtBlock>>>(w1, w2, p_Wb1, p_Wb2);
    k_gnstats<<<gnBlocks, 256>>>(x, bid, N);
    k_gnfinal<<<1, 256>>>(0);
    k_gn_silu_h<<<(t4 + 255) / 256, 256>>>(x, p_h, gn1w, gn1b, bid, N);

    // --- join: conv1 GEMM ---
    cudaStreamWaitEvent(0, evA, 0);
    k_gemm_h<<<gemmGrid, 128>>>(p_h, p_Wb1, p_Y);
    cudaStreamWaitEvent(0, evB, 0);
    k_gather_gn<<<gatherBlocks, 256>>>(p_Y, p_acch, bid, N);

    // --- GN2 + silu ---
    k_gnfinal<<<1, 256>>>(1);
    k_gn_silu_hh<<<(t4 + 255) / 256, 256>>>(p_acch, p_h, gn2w, gn2b, bid, N);

    // --- conv2 + fused residual ---
    k_gemm_h<<<gemmGrid, 128>>>(p_h, p_Wb2, p_Y);
    k_gather<<<gatherBlocks, 256>>>(p_Y, x, (float*)d_out, N);

    cudaStreamCaptureStatus cap = cudaStreamCaptureStatusNone;
    cudaStreamIsCapturing(s2, &cap);
    if (cap == cudaStreamCaptureStatusNone) {
        cudaEventDestroy(evFork);
        cudaEventDestroy(evA);
        cudaEventDestroy(evB);
        cudaStreamDestroy(s2);
    }
}

// round 15
// speedup vs baseline: 1.2772x; 1.2772x over previous
#include <cuda_runtime.h>
#include <cuda_fp16.h>
#include <stdint.h>

#define C_DIM   256
#define NGROUP  32
#define CPG     8
#define NET     7
#define NBATCH  8
#define GN_EPS  1e-5f
#define MAXN    100000
#define MAXE    1048576
#define N7MAX   (MAXN * NET)
#define NPB     128
#define SCAN_B  2048

// ---------------- scratch ----------------
__device__ __half  g_h  [(size_t)MAXN * C_DIM];            // fp16 GEMM input
__device__ __half  g_acch[(size_t)MAXN * C_DIM];           // conv1 output (fp16)
__device__ __half  g_Y  [(size_t)(N7MAX + 1024) * C_DIM];  // compacted fp16 intermediate
__device__ __half  g_Wb1[NET * C_DIM * C_DIM];             // packed W1: [t][n][k] fp16
__device__ __half  g_Wb2[NET * C_DIM * C_DIM];
__device__ int     g_cnt[MAXN * NET];      // per (row, type) in-degree
__device__ int     g_rowcnt[MAXN];
__device__ int     g_offs[MAXN];
__device__ int     g_cur[MAXN];
__device__ int     g_blksum[64];
__device__ int     g_eperm[MAXE];          // (pos<<3) | type
// --- compaction state ---
__device__ int     g_need[N7MAX];
__device__ int     g_cpos[N7MAX];
__device__ int     g_blksum2[512];
__device__ int     g_pos [N7MAX];
__device__ int     g_clist[N7MAX + 1024];
__device__ int     g_tpadA[8];
__device__ int     g_tstart[8];
__device__ int     g_mtotal;
// --- GN state ---
__device__ float   g_s1 [NBATCH * NGROUP];
__device__ float   g_s2 [NBATCH * NGROUP];
__device__ float   g_mean[NBATCH * NGROUP];
__device__ float   g_istd[NBATCH * NGROUP];
__device__ float   g_bcnt[NBATCH];         // maintained zero-at-entry across launches

// ---------------- init (+ batch count fused) ----------------
__global__ void k_init(const int* __restrict__ bid, int N, int n7) {
    __shared__ int sc[NBATCH];
    if (threadIdx.x < NBATCH) sc[threadIdx.x] = 0;
    __syncthreads();
    int i = blockIdx.x * blockDim.x + threadIdx.x;
    if (i < n7) { g_cnt[i] = 0; g_need[i] = 0; }
    if (i < n7 + 1024) g_clist[i] = -1;
    if (i < N) { g_cur[i] = 0; atomicAdd(&sc[bid[i]], 1); }
    if (i < NBATCH * NGROUP) { g_s1[i] = 0.f; g_s2[i] = 0.f; }
    __syncthreads();
    if (threadIdx.x < NBATCH && sc[threadIdx.x] > 0)
        atomicAdd(&g_bcnt[threadIdx.x], (float)sc[threadIdx.x]);
}

// ---------------- W pack+transpose, both weights in one launch ----------------
__global__ void k_wpackT2(const float* __restrict__ W1, const float* __restrict__ W2,
                          __half* __restrict__ Wb1, __half* __restrict__ Wb2) {
    __shared__ float tile[32][33];
    int z = blockIdx.z;
    const float* W = (z < NET) ? W1 : W2;
    __half* Wb     = (z < NET) ? Wb1 : Wb2;
    int t = (z < NET) ? z : z - NET;
    int k0 = blockIdx.x * 32, n0 = blockIdx.y * 32;
    for (int j = threadIdx.y; j < 32; j += 8)
        tile[j][threadIdx.x] = W[(size_t)(t * 256 + k0 + j) * C_DIM + n0 + threadIdx.x];
    __syncthreads();
    for (int j = threadIdx.y; j < 32; j += 8)
        Wb[((size_t)t * 256 + n0 + j) * C_DIM + k0 + threadIdx.x] =
            __float2half_rn(tile[threadIdx.x][j]);
}

// ---------------- GN ----------------
__global__ void k_gnstats(const float* __restrict__ src, const int* __restrict__ bid, int N) {
    __shared__ int sbid[NPB];
    int n0 = blockIdx.x * NPB;
    int nmax = min(N - n0, NPB);
    for (int i = threadIdx.x; i < nmax; i += blockDim.x) sbid[i] = bid[n0 + i];
    __syncthreads();
    int c = threadIdx.x;
    int g = c >> 3;
    float ls1 = 0.f, ls2 = 0.f;
    int cur = sbid[0];
    for (int i = 0; i < nmax; ++i) {
        int b = sbid[i];
        if (b != cur) {
            atomicAdd(&g_s1[cur * NGROUP + g], ls1);
            atomicAdd(&g_s2[cur * NGROUP + g], ls2);
            ls1 = 0.f; ls2 = 0.f; cur = b;
        }
        float v = src[(size_t)(n0 + i) * C_DIM + c];
        ls1 += v; ls2 += v * v;
    }
    atomicAdd(&g_s1[cur * NGROUP + g], ls1);
    atomicAdd(&g_s2[cur * NGROUP + g], ls2);
}
__global__ void k_gnfinal(int zero_bcnt) {
    int i = threadIdx.x;
    int b = i >> 5;
    float n  = g_bcnt[b] * (float)CPG;
    float ic = 1.0f / (n + GN_EPS);
    float s1 = g_s1[i], s2 = g_s2[i];
    float m  = s1 * ic;
    float var = ic * (s2 - 2.f * m * s1 + m * m * n);
    g_mean[i] = m;
    g_istd[i] = rsqrtf(var + GN_EPS);
    __syncthreads();
    g_s1[i] = 0.f; g_s2[i] = 0.f;
    if (zero_bcnt && i < NBATCH) g_bcnt[i] = 0.f;
}
__global__ void k_gn_silu_h(const float* __restrict__ src, __half* __restrict__ dst,
                            const float* __restrict__ w, const float* __restrict__ bb,
                            const int* __restrict__ bid, int N) {
    int i = blockIdx.x * blockDim.x + threadIdx.x;
    int total = N * (C_DIM / 4);
    if (i >= total) return;
    int n  = i >> 6;
    int c4 = (i & 63) << 2;
    int b  = bid[n];
    int s  = b * NGROUP + (c4 >> 3);
    float m  = g_mean[s], is = g_istd[s];
    float4 xv = ((const float4*)src)[i];
    float4 wv = ((const float4*)w)[c4 >> 2];
    float4 bv = ((const float4*)bb)[c4 >> 2];
    float v0 = (xv.x - m) * is * wv.x + bv.x; v0 = v0 / (1.f + expf(-v0));
    float v1 = (xv.y - m) * is * wv.y + bv.y; v1 = v1 / (1.f + expf(-v1));
    float v2 = (xv.z - m) * is * wv.z + bv.z; v2 = v2 / (1.f + expf(-v2));
    float v3 = (xv.w - m) * is * wv.w + bv.w; v3 = v3 / (1.f + expf(-v3));
    __half2 h[2];
    h[0] = __floats2half2_rn(v0, v1);
    h[1] = __floats2half2_rn(v2, v3);
    *(uint2*)(dst + (size_t)n * C_DIM + c4) = *(uint2*)h;
}
__global__ void k_gn_silu_hh(const __half* __restrict__ src, __half* __restrict__ dst,
                             const float* __restrict__ w, const float* __restrict__ bb,
                             const int* __restrict__ bid, int N) {
    int i = blockIdx.x * blockDim.x + threadIdx.x;
    int total = N * (C_DIM / 4);
    if (i >= total) return;
    int n  = i >> 6;
    int c4 = (i & 63) << 2;
    int b  = bid[n];
    int s  = b * NGROUP + (c4 >> 3);
    float m  = g_mean[s], is = g_istd[s];
    uint2 raw = *(const uint2*)(src + (size_t)n * C_DIM + c4);
    const __half2* hp = (const __half2*)&raw;
    float2 f0 = __half22float2(hp[0]);
    float2 f1 = __half22float2(hp[1]);
    float4 wv = ((const float4*)w)[c4 >> 2];
    float4 bv = ((const float4*)bb)[c4 >> 2];
    float v0 = (f0.x - m) * is * wv.x + bv.x; v0 = v0 / (1.f + expf(-v0));
    float v1 = (f0.y - m) * is * wv.y + bv.y; v1 = v1 / (1.f + expf(-v1));
    float v2 = (f1.x - m) * is * wv.z + bv.z; v2 = v2 / (1.f + expf(-v2));
    float v3 = (f1.y - m) * is * wv.w + bv.w; v3 = v3 / (1.f + expf(-v3));
    __half2 h[2];
    h[0] = __floats2half2_rn(v0, v1);
    h[1] = __floats2half2_rn(v2, v3);
    *(uint2*)(dst + (size_t)n * C_DIM + c4) = *(uint2*)h;
}

// ---------------- edge count + needed-bitmap ----------------
__global__ void k_ecount2(const int* __restrict__ erow, const int* __restrict__ ecol,
                          const int* __restrict__ et, int E, int N) {
    int e = blockIdx.x * blockDim.x + threadIdx.x;
    if (e < E) {
        int r = erow[e], t = et[e];
        atomicAdd(&g_cnt[r * NET + t], 1);
        g_need[t * N + ecol[e]] = 1;
    }
}
__global__ void k_scan1(int N) {
    __shared__ int sh[256];
    int base = blockIdx.x * SCAN_B;
    int tid = threadIdx.x;
    int vals[8];
    int s = 0;
    #pragma unroll
    for (int j = 0; j < 8; ++j) {
        int idx = base + tid * 8 + j;
        int v = 0;
        if (idx < N) {
            const int* cp = &g_cnt[idx * NET];
            #pragma unroll
            for (int q = 0; q < NET; ++q) v += cp[q];
            g_rowcnt[idx] = v;
        }
        vals[j] = s;
        s += v;
    }
    sh[tid] = s;
    __syncthreads();
    for (int off = 1; off < 256; off <<= 1) {
        int t = (tid >= off) ? sh[tid - off] : 0;
        __syncthreads();
        sh[tid] += t;
        __syncthreads();
    }
    int tb = tid ? sh[tid - 1] : 0;
    #pragma unroll
    for (int j = 0; j < 8; ++j) {
        int idx = base + tid * 8 + j;
        if (idx < N) g_offs[idx] = tb + vals[j];
    }
    if (tid == 255) g_blksum[blockIdx.x] = sh[255];
}
__global__ void k_scan2(int nb) {
    __shared__ int sh[64];
    int t = threadIdx.x;
    sh[t] = (t < nb) ? g_blksum[t] : 0;
    __syncthreads();
    for (int off = 1; off < 64; off <<= 1) {
        int v = (t >= off) ? sh[t - off] : 0;
        __syncthreads();
        sh[t] += v;
        __syncthreads();
    }
    if (t < nb) g_blksum[t] = t ? sh[t - 1] : 0;
}
__global__ void k_scan1b(int M) {
    __shared__ int sh[256];
    int base = blockIdx.x * SCAN_B;
    int tid = threadIdx.x;
    int vals[8];
    int s = 0;
    #pragma unroll
    for (int j = 0; j < 8; ++j) {
        int idx = base + tid * 8 + j;
        int v = (idx < M && g_need[idx]) ? 1 : 0;
        vals[j] = s;
        s += v;
    }
    sh[tid] = s;
    __syncthreads();
    for (int off = 1; off < 256; off <<= 1) {
        int t = (tid >= off) ? sh[tid - off] : 0;
        __syncthreads();
        sh[tid] += t;
        __syncthreads();
    }
    int tb = tid ? sh[tid - 1] : 0;
    #pragma unroll
    for (int j = 0; j < 8; ++j) {
        int idx = base + tid * 8 + j;
        if (idx < M) g_cpos[idx] = tb + vals[j];
    }
    if (tid == 255) g_blksum2[blockIdx.x] = sh[255];
}
__global__ void k_scan2b(int nb, int N, int n7) {
    __shared__ int sh[512];
    int t = threadIdx.x;
    sh[t] = (t < nb) ? g_blksum2[t] : 0;
    __syncthreads();
    for (int off = 1; off < 512; off <<= 1) {
        int v = (t >= off) ? sh[t - off] : 0;
        __syncthreads();
        sh[t] += v;
        __syncthreads();
    }
    if (t < nb) g_blksum2[t] = t ? sh[t - 1] : 0;
    __syncthreads();
    if (t == 0) {
        int tstart[8];
        for (int q = 0; q < NET; ++q) {
            int idx = q * N;
            tstart[q] = g_cpos[idx] + g_blksum2[idx / SCAN_B];
        }
        int last = n7 - 1;
        tstart[7] = g_cpos[last] + g_blksum2[last / SCAN_B] + (g_need[last] ? 1 : 0);
        int tp = 0;
        for (int q = 0; q < NET; ++q) {
            g_tstart[q] = tstart[q];
            g_tpadA[q] = tp;
            tp += (tstart[q + 1] - tstart[q] + 127) & ~127;
        }
        g_tstart[7] = tstart[7];
        g_tpadA[7] = tp;
        g_mtotal = tp;
    }
}
__global__ void k_fillpos(int N, int n7) {
    int i = blockIdx.x * blockDim.x + threadIdx.x;
    if (i >= n7 || !g_need[i]) return;
    int t = i / N, c = i - t * N;
    int pos = g_tpadA[t] + g_cpos[i] + g_blksum2[i / SCAN_B] - g_tstart[t];
    g_pos[i] = pos;
    g_clist[pos] = c;
}
__global__ void k_escatter(const int* __restrict__ erow, const int* __restrict__ ecol,
                           const int* __restrict__ et, int E, int N) {
    int e = blockIdx.x * blockDim.x + threadIdx.x;
    if (e >= E) return;
    int r = erow[e], t = et[e];
    int posIdx = g_offs[r] + g_blksum[r >> 11] + atomicAdd(&g_cur[r], 1);
    int pos = g_pos[t * N + ecol[e]];
    g_eperm[posIdx] = (pos << 3) | t;
}

// ---------------- fp16 GEMM (R12 proven config): BM=128/BN=128, 256thr, 3-stage ----------------
#define BM 128
#define BN 128
#define BK 32
#define KSTR 40
#define TILE_B (128 * KSTR * 2)
#define STAGE_B (2 * TILE_B)
#define NSTAGE 3
#define EPS_LD 136

__device__ __forceinline__ void mma_f16(float* d, const uint32_t* a, uint32_t b0, uint32_t b1) {
    asm volatile("mma.sync.aligned.m16n8k16.row.col.f32.f16.f16.f32 "
        "{%0,%1,%2,%3}, {%4,%5,%6,%7}, {%8,%9}, {%0,%1,%2,%3};\n"
        : "+f"(d[0]), "+f"(d[1]), "+f"(d[2]), "+f"(d[3])
        : "r"(a[0]), "r"(a[1]), "r"(a[2]), "r"(a[3]), "r"(b0), "r"(b1));
}
__device__ __forceinline__ void ldsm_x4(uint32_t* r, uint32_t addr) {
    asm volatile("ldmatrix.sync.aligned.m8n8.x4.shared.b16 {%0,%1,%2,%3}, [%4];\n"
        : "=r"(r[0]), "=r"(r[1]), "=r"(r[2]), "=r"(r[3]) : "r"(addr));
}

__global__ __launch_bounds__(256, 2)
void k_gemm_h(const __half* __restrict__ A, const __half* __restrict__ Wb,
              __half* __restrict__ Y) {
    int m0 = blockIdx.y * BM;
    if (m0 >= g_mtotal) return;

    __shared__ __align__(16) char sm[NSTAGE * STAGE_B];

    int tid  = threadIdx.x;
    int warp = tid >> 5, lane = tid & 31;
    int n0 = blockIdx.x * BN;

    int t = 0;
    #pragma unroll
    for (int q = 1; q < NET; ++q) t += (m0 >= g_tpadA[q]) ? 1 : 0;
    const __half* gB = Wb + ((size_t)t * 256 + n0) * C_DIM;

    int wm = warp >> 1, wn = warp & 1;
    int mBase = wm * 32, nBase = wn * 64;
    int grp = lane >> 2, tig = lane & 3;
    int mi = lane >> 3, lr = lane & 7;

    uint32_t sbase = (uint32_t)__cvta_generic_to_shared(sm);

    float acc[2][8][4];
    #pragma unroll
    for (int i = 0; i < 2; ++i)
        #pragma unroll
        for (int j = 0; j < 8; ++j)
            #pragma unroll
            for (int q = 0; q < 4; ++q) acc[i][j][q] = 0.f;

    int cRowA = tid >> 2, cQ = tid & 3;
    int cRowA2 = cRowA + 64;
    int col0 = g_clist[m0 + cRowA];
    int col1 = g_clist[m0 + cRowA2];

    auto issue = [&](int st, int kb) {
        uint32_t sa = sbase + st * STAGE_B;
        uint32_t sb = sa + TILE_B;
        {
            uint32_t d0 = sa + cRowA * (KSTR * 2) + cQ * 16;
            int z0 = (col0 >= 0) ? 16 : 0;
            const __half* p0 = z0 ? (A + (size_t)col0 * C_DIM + kb + cQ * 8) : A;
            asm volatile("cp.async.cg.shared.global [%0], [%1], 16, %2;\n"
                :: "r"(d0), "l"(p0), "r"(z0) : "memory");
            uint32_t d1 = sa + cRowA2 * (KSTR * 2) + cQ * 16;
            int z1 = (col1 >= 0) ? 16 : 0;
            const __half* p1 = z1 ? (A + (size_t)col1 * C_DIM + kb + cQ * 8) : A;
            asm volatile("cp.async.cg.shared.global [%0], [%1], 16, %2;\n"
                :: "r"(d1), "l"(p1), "r"(z1) : "memory");
        }
        {
            uint32_t d0 = sb + cRowA * (KSTR * 2) + cQ * 16;
            const __half* s0 = gB + (size_t)cRowA * C_DIM + kb + cQ * 8;
            asm volatile("cp.async.cg.shared.global [%0], [%1], 16, 16;\n"
                :: "r"(d0), "l"(s0) : "memory");
            uint32_t d1 = sb + cRowA2 * (KSTR * 2) + cQ * 16;
            const __half* s1 = gB + (size_t)cRowA2 * C_DIM + kb + cQ * 8;
            asm volatile("cp.async.cg.shared.global [%0], [%1], 16, 16;\n"
                :: "r"(d1), "l"(s1) : "memory");
        }
        asm volatile("cp.async.commit_group;\n" ::: "memory");
    };

    auto compute = [&](int st) {
        uint32_t sa = sbase + st * STAGE_B;
        uint32_t sb = sa + TILE_B;
        #pragma unroll
        for (int ks = 0; ks < 2; ++ks) {
            int k0 = ks * 16;
            uint32_t a[2][4];
            #pragma unroll
            for (int im = 0; im < 2; ++im) {
                int row = mBase + im * 16 + ((mi & 1) << 3) + lr;
                int col = k0 + ((mi >> 1) << 3);
                ldsm_x4(a[im], sa + (uint32_t)(row * KSTR + col) * 2);
            }
            #pragma unroll
            for (int nb = 0; nb < 4; ++nb) {
                uint32_t b[4];
                int row = nBase + nb * 16 + ((mi >> 1) << 3) + lr;
                int col = k0 + ((mi & 1) << 3);
                ldsm_x4(b, sb + (uint32_t)(row * KSTR + col) * 2);
                mma_f16(acc[0][nb * 2],     a[0], b[0], b[1]);
                mma_f16(acc[1][nb * 2],     a[1], b[0], b[1]);
                mma_f16(acc[0][nb * 2 + 1], a[0], b[2], b[3]);
                mma_f16(acc[1][nb * 2 + 1], a[1], b[2], b[3]);
            }
        }
    };

    issue(0, 0);
    issue(1, BK);
    #pragma unroll
    for (int it = 0; it < 8; ++it) {
        if (it + 2 < 8) {
            asm volatile("cp.async.wait_group 1;\n" ::: "memory");
        } else {
            asm volatile("cp.async.wait_group 0;\n" ::: "memory");
        }
        __syncthreads();
        if (it + 2 < 8) issue((it + 2) % 3, (it + 2) * BK);
        compute(it % 3);
    }

    __syncthreads();
    __half* ep = (__half*)sm;
    #pragma unroll
    for (int im = 0; im < 2; ++im) {
        int r = mBase + im * 16 + grp;
        #pragma unroll
        for (int in = 0; in < 8; ++in) {
            int cc = nBase + in * 8 + tig * 2;
            *(__half2*)(ep + r * EPS_LD + cc) =
                __floats2half2_rn(acc[im][in][0], acc[im][in][1]);
            *(__half2*)(ep + (r + 8) * EPS_LD + cc) =
                __floats2half2_rn(acc[im][in][2], acc[im][in][3]);
        }
    }
    __syncthreads();
    #pragma unroll
    for (int j = 0; j < 8; ++j) {
        int idx = tid + j * 256;
        int row = idx >> 4, u = idx & 15;
        *(uint4*)(Y + (size_t)(m0 + row) * C_DIM + n0 + u * 8) =
            *(const uint4*)(ep + row * EPS_LD + u * 8);
    }
}

// ---------------- gather core: 2-edge unrolled, MLP=2 ----------------
__device__ __forceinline__ void gather_row2(const __half* __restrict__ Y, int w, int lane,
                                            float* acc) {
    int beg = g_offs[w] + g_blksum[w >> 11];
    int deg = g_rowcnt[w];
    const int* cntp = &g_cnt[w * NET];
    int j = 0;
    for (; j + 2 <= deg; j += 2) {
        int p0 = g_eperm[beg + j];
        int p1 = g_eperm[beg + j + 1];
        uint4 v0 = *((const uint4*)(Y + (size_t)(p0 >> 3) * C_DIM) + lane);
        uint4 v1 = *((const uint4*)(Y + (size_t)(p1 >> 3) * C_DIM) + lane);
        float i0 = 1.f / (float)cntp[p0 & 7];
        float i1 = 1.f / (float)cntp[p1 & 7];
        const __half2* h0 = (const __half2*)&v0;
        const __half2* h1 = (const __half2*)&v1;
        #pragma unroll
        for (int q = 0; q < 4; ++q) {
            float2 f0 = __half22float2(h0[q]);
            float2 f1 = __half22float2(h1[q]);
            acc[q * 2 + 0] += f0.x * i0 + f1.x * i1;
            acc[q * 2 + 1] += f0.y * i0 + f1.y * i1;
        }
    }
    if (j < deg) {
        int p0 = g_eperm[beg + j];
        uint4 v0 = *((const uint4*)(Y + (size_t)(p0 >> 3) * C_DIM) + lane);
        float i0 = 1.f / (float)cntp[p0 & 7];
        const __half2* h0 = (const __half2*)&v0;
        #pragma unroll
        for (int q = 0; q < 4; ++q) {
            float2 f0 = __half22float2(h0[q]);
            acc[q * 2 + 0] += f0.x * i0;
            acc[q * 2 + 1] += f0.y * i0;
        }
    }
}

// ---------------- conv1 gather: fp16 out + fused GN2 stats (lane == group) ----------------
__global__ void k_gather_gn(const __half* __restrict__ Y, __half* __restrict__ outh,
                            const int* __restrict__ bid, int N) {
    __shared__ float sh1[NBATCH * NGROUP], sh2[NBATCH * NGROUP];
    int tid = threadIdx.x;
    sh1[tid] = 0.f; sh2[tid] = 0.f;
    __syncthreads();

    int w = (blockIdx.x * blockDim.x + tid) >> 5;
    int lane = tid & 31;
    if (w < N) {
        float acc[8] = {0.f, 0.f, 0.f, 0.f, 0.f, 0.f, 0.f, 0.f};
        gather_row2(Y, w, lane, acc);
        __half2 ho[4];
        #pragma unroll
        for (int q = 0; q < 4; ++q)
            ho[q] = __floats2half2_rn(acc[q * 2], acc[q * 2 + 1]);
        *(uint4*)(outh + (size_t)w * C_DIM + lane * 8) = *(uint4*)ho;

        float ls1 = 0.f, ls2 = 0.f;
        #pragma unroll
        for (int q = 0; q < 8; ++q) { ls1 += acc[q]; ls2 += acc[q] * acc[q]; }
        int b = bid[w];
        atomicAdd(&sh1[b * NGROUP + lane], ls1);
        atomicAdd(&sh2[b * NGROUP + lane], ls2);
    }
    __syncthreads();
    float v1 = sh1[tid], v2 = sh2[tid];
    if (v1 != 0.f) atomicAdd(&g_s1[tid], v1);
    if (v2 != 0.f) atomicAdd(&g_s2[tid], v2);
}

// ---------------- conv2 gather: fp32 out + residual ----------------
__global__ void k_gather(const __half* __restrict__ Y, const float* __restrict__ resid,
                         float* __restrict__ out, int N) {
    int w = (blockIdx.x * blockDim.x + threadIdx.x) >> 5;
    int lane = threadIdx.x & 31;
    if (w >= N) return;
    float acc[8] = {0.f, 0.f, 0.f, 0.f, 0.f, 0.f, 0.f, 0.f};
    gather_row2(Y, w, lane, acc);
    const float* rp = resid + (size_t)w * C_DIM + lane * 8;
    float4 r0 = *(const float4*)rp, r1 = *(const float4*)(rp + 4);
    acc[0] += r0.x; acc[1] += r0.y; acc[2] += r0.z; acc[3] += r0.w;
    acc[4] += r1.x; acc[5] += r1.y; acc[6] += r1.z; acc[7] += r1.w;
    float* orow = out + (size_t)w * C_DIM + lane * 8;
    *(float4*)orow       = make_float4(acc[0], acc[1], acc[2], acc[3]);
    *(float4*)(orow + 4) = make_float4(acc[4], acc[5], acc[6], acc[7]);
}

// ---------------- launch ----------------
extern "C" void kernel_launch(void* const* d_in, const int* in_sizes, int n_in,
                              void* d_out, int out_size) {
    const float* x    = (const float*)d_in[0];
    const float* gn1w = (const float*)d_in[1];
    const float* gn1b = (const float*)d_in[2];
    const float* w1   = (const float*)d_in[3];
    const float* gn2w = (const float*)d_in[4];
    const float* gn2b = (const float*)d_in[5];
    const float* w2   = (const float*)d_in[6];
    const int*   eidx = (const int*)d_in[7];
    const int*   et   = (const int*)d_in[8];
    const int*   bid  = (const int*)d_in[9];

    int N = in_sizes[0] / C_DIM;
    int E = in_sizes[8];
    const int* erow = eidx;
    const int* ecol = eidx + E;

    __half *p_h, *p_acch, *p_Y, *p_Wb1, *p_Wb2;
    cudaGetSymbolAddress((void**)&p_h,    g_h);
    cudaGetSymbolAddress((void**)&p_acch, g_acch);
    cudaGetSymbolAddress((void**)&p_Y,    g_Y);
    cudaGetSymbolAddress((void**)&p_Wb1,  g_Wb1);
    cudaGetSymbolAddress((void**)&p_Wb2,  g_Wb2);

    int n7 = N * NET;
    int t4 = N * (C_DIM / 4);
    int gnBlocks = (N + NPB - 1) / NPB;
    int nbScan  = (N + SCAN_B - 1) / SCAN_B;
    int nbScanB = (n7 + SCAN_B - 1) / SCAN_B;
    int maxYBlocks = (n7 + NET * 128 + BM - 1) / BM;
    dim3 gemmGrid(2, maxYBlocks);
    int gatherBlocks = (N + 7) / 8;
    dim3 wtGrid(8, 8, 2 * NET), wtBlock(32, 8);

    // forked side stream so the CSR/compaction branch runs concurrently with GN1
    cudaStream_t s2;
    cudaStreamCreateWithFlags(&s2, cudaStreamNonBlocking);
    cudaEvent_t evFork, evA, evB;
    cudaEventCreateWithFlags(&evFork, cudaEventDisableTiming);
    cudaEventCreateWithFlags(&evA, cudaEventDisableTiming);
    cudaEventCreateWithFlags(&evB, cudaEventDisableTiming);

    // --- common init ---
    k_init<<<(n7 + 1024 + 255) / 256, 256>>>(bid, N, n7);
    cudaEventRecord(evFork, 0);
    cudaStreamWaitEvent(s2, evFork, 0);

    // --- branch A (s2): CSR + compaction ---
    k_ecount2<<<(E + 255) / 256, 256, 0, s2>>>(erow, ecol, et, E, N);
    k_scan1<<<nbScan, 256, 0, s2>>>(N);
    k_scan2<<<1, 64, 0, s2>>>(nbScan);
    k_scan1b<<<nbScanB, 256, 0, s2>>>(n7);
    k_scan2b<<<1, 512, 0, s2>>>(nbScanB, N, n7);
    k_fillpos<<<(n7 + 255) / 256, 256, 0, s2>>>(N, n7);
    cudaEventRecord(evA, s2);              // GEMM needs tpadA/mtotal/clist
    k_escatter<<<(E + 255) / 256, 256, 0, s2>>>(erow, ecol, et, E, N);
    cudaEventRecord(evB, s2);              // gathers need eperm

    // --- branch B (main): W pack + GN1 + silu ---
    k_wpackT2<<<wtGrid, wtBlock>>>(w1, w2, p_Wb1, p_Wb2);
    k_gnstats<<<gnBlocks, 256>>>(x, bid, N);
    k_gnfinal<<<1, 256>>>(0);
    k_gn_silu_h<<<(t4 + 255) / 256, 256>>>(x, p_h, gn1w, gn1b, bid, N);

    // --- join: conv1 GEMM ---
    cudaStreamWaitEvent(0, evA, 0);
    k_gemm_h<<<gemmGrid, 256>>>(p_h, p_Wb1, p_Y);
    cudaStreamWaitEvent(0, evB, 0);
    k_gather_gn<<<gatherBlocks, 256>>>(p_Y, p_acch, bid, N);

    // --- GN2 + silu ---
    k_gnfinal<<<1, 256>>>(1);
    k_gn_silu_hh<<<(t4 + 255) / 256, 256>>>(p_acch, p_h, gn2w, gn2b, bid, N);

    // --- conv2 + fused residual ---
    k_gemm_h<<<gemmGrid, 256>>>(p_h, p_Wb2, p_Y);
    k_gather<<<gatherBlocks, 256>>>(p_Y, x, (float*)d_out, N);

    cudaStreamCaptureStatus cap = cudaStreamCaptureStatusNone;
    cudaStreamIsCapturing(s2, &cap);
    if (cap == cudaStreamCaptureStatusNone) {
        cudaEventDestroy(evFork);
        cudaEventDestroy(evA);
        cudaEventDestroy(evB);
        cudaStreamDestroy(s2);
    }
}